// round 7
// baseline (speedup 1.0000x reference)
#include <cuda_runtime.h>
#include <cuda_bf16.h>

// ---------------- problem constants ----------------
#define BB   4
#define TT   16
#define NN   1000
#define FIN  8
#define EE   8000
#define EP   9000          // edges + self loops
#define HID  64
#define HEADS 4
#define LL   5
#define GG   64            // B*T graphs
#define RR   64000         // G*N rows
#define NH   64000         // N*HID
#define GATES 192
#define KCH  512
#define NCHUNK 125

#define AGG4_SMEM (NN * 16 * 4)   // 64000 B

// H layout: slice-major. Column c of row r lives at
//   g_H[(c>>4) * (RR*16) + r*16 + (c&15)]
#define HSLICE (RR * 16)

// ---------------- device scratch ----------------
__device__ float g_X0[RR * HID];
__device__ float g_X1[RR * HID];
__device__ float g_H [16 * HSLICE];
__device__ float g_ls[RR * HEADS];
__device__ float g_ld[RR * HEADS];
__device__ int   g_off[NN + 1];
__device__ int   g_srcList[EP];
__device__ int   g_eid[EP];
__device__ float2 g_ew[GG * HEADS * EP];     // (expWeight, srcBits) per edge
__device__ float g_snorm[GG * HEADS * NN];   // 1/sum per (g,h,node)
__device__ float g_GIpart[NCHUNK * GG * GATES];
__device__ float g_GI[GG * GATES];
__device__ float g_hT[BB * HID];

// ---------------- fused pre-kernel: CSR build (block 4000) + input proj ------
__global__ void __launch_bounds__(1024) k_pre(const int* __restrict__ edge_index,
                                              const float* __restrict__ x,
                                              const float* __restrict__ W_in,
                                              const float* __restrict__ b_in) {
    int tid = threadIdx.x;
    if (blockIdx.x < 4000) {
        // input projection: 16 rows x 64 channels per block
        int r = blockIdx.x * 16 + (tid >> 6);
        int c = tid & 63;
        float s = b_in[c];
#pragma unroll
        for (int f = 0; f < FIN; f++)
            s += x[r * FIN + f] * W_in[f * HID + c];
        g_X0[r * HID + c] = s;
        return;
    }
    // ---- CSR build (deterministic), one block ----
    __shared__ int scnt[1024];
    __shared__ int sscan[1024];
    __shared__ int scur[1024];
    scnt[tid] = 0;
    __syncthreads();
    for (int e = tid; e < EE; e += 1024)
        atomicAdd(&scnt[edge_index[EE + e]], 1);
    __syncthreads();
    int v = (tid < NN) ? (scnt[tid] + 1) : 0;    // +1 self loop
    sscan[tid] = v;
    __syncthreads();
    for (int o = 1; o < 1024; o <<= 1) {
        int add = (tid >= o) ? sscan[tid - o] : 0;
        __syncthreads();
        sscan[tid] += add;
        __syncthreads();
    }
    if (tid < NN) {
        g_off[tid + 1] = sscan[tid];
        scur[tid] = (tid == 0) ? 0 : sscan[tid - 1];
    }
    if (tid == 0) g_off[0] = 0;
    __syncthreads();
    for (int e = tid; e < EP; e += 1024) {
        int s, d;
        if (e < EE) { s = edge_index[e]; d = edge_index[EE + e]; }
        else        { s = e - EE;        d = e - EE; }
        int pos = atomicAdd(&scur[d], 1);
        g_srcList[pos] = s;
        g_eid[pos] = e;
    }
    __syncthreads();
    if (tid < NN) {                       // stable order by edge id
        int s0 = g_off[tid], s1 = g_off[tid + 1];
        for (int i = s0 + 1; i < s1; i++) {
            int id = g_eid[i], sv = g_srcList[i];
            int j = i - 1;
            while (j >= s0 && g_eid[j] > id) {
                g_eid[j + 1] = g_eid[j];
                g_srcList[j + 1] = g_srcList[j];
                j--;
            }
            g_eid[j + 1] = id;
            g_srcList[j + 1] = sv;
        }
    }
}

// ---------------- GAT GEMM + fused ls/ld epilogue ----------------------------
__global__ void __launch_bounds__(256) k_gat_gemm(int inBuf, const float* __restrict__ W,
                                                  const float* __restrict__ asrc,
                                                  const float* __restrict__ adst) {
    __shared__ float sm[12288];                 // 48KB, aliased
    float (*As)[64]  = (float(*)[64])sm;        // [64][64]
    float (*Ws)[256] = (float(*)[256])(sm + 4096); // [32][256]
    const float* __restrict__ X = inBuf ? g_X1 : g_X0;
    int rowBase = blockIdx.x * 64;
    int tid = threadIdx.x;

    const float4* X4 = (const float4*)(X + (size_t)rowBase * 64);
#pragma unroll
    for (int q = 0; q < 4; q++) {
        int idx = tid + q * 256;
        int r = idx & 63, k4 = idx >> 6;
        float4 v = X4[r * 16 + k4];
        As[k4 * 4 + 0][r] = v.x;
        As[k4 * 4 + 1][r] = v.y;
        As[k4 * 4 + 2][r] = v.z;
        As[k4 * 4 + 3][r] = v.w;
    }

    int lane = tid & 31, w = tid >> 5;
    int ry2 = lane >> 2, cx2 = lane & 3;
    int cg = w * 4 + cx2;                       // 0..31
    float acc[8][8] = {};
    const float4* W4 = (const float4*)W;

#pragma unroll
    for (int half = 0; half < 2; half++) {
        __syncthreads();
#pragma unroll
        for (int q = 0; q < 8; q++) {
            int idx = tid + q * 256;
            ((float4*)Ws)[idx] = W4[half * 2048 + idx];
        }
        __syncthreads();
#pragma unroll
        for (int kk = 0; kk < 32; kk++) {
            int k = half * 32 + kk;
            float4 a0 = *(const float4*)&As[k][ry2 * 4];
            float4 a1 = *(const float4*)&As[k][32 + ry2 * 4];
            float4 b0 = *(const float4*)&Ws[kk][cg * 4];
            float4 b1 = *(const float4*)&Ws[kk][128 + cg * 4];
            float av[8] = {a0.x, a0.y, a0.z, a0.w, a1.x, a1.y, a1.z, a1.w};
            float bv[8] = {b0.x, b0.y, b0.z, b0.w, b1.x, b1.y, b1.z, b1.w};
#pragma unroll
            for (int i = 0; i < 8; i++)
#pragma unroll
                for (int j = 0; j < 8; j++)
                    acc[i][j] += av[i] * bv[j];
        }
    }
    // store H in slice-major layout
    {
        int slLo = cg >> 2, slHi = 8 + (cg >> 2);
        int chB = (cg & 3) * 4;
#pragma unroll
        for (int i = 0; i < 8; i++) {
            int r = rowBase + ((i < 4) ? (ry2 * 4 + i) : (32 + ry2 * 4 + (i - 4)));
            *(float4*)&g_H[(size_t)slLo * HSLICE + r * 16 + chB] =
                make_float4(acc[i][0], acc[i][1], acc[i][2], acc[i][3]);
            *(float4*)&g_H[(size_t)slHi * HSLICE + r * 16 + chB] =
                make_float4(acc[i][4], acc[i][5], acc[i][6], acc[i][7]);
        }
    }

    // ---- fused ls/ld epilogue ----
    __syncthreads();                            // done reading As/Ws
    float (*redls)[4][16] = (float(*)[4][16])sm;          // [64][4][16]
    float (*redld)[4][16] = (float(*)[4][16])(sm + 4096);
    float as_lo[4], as_hi[4], ad_lo[4], ad_hi[4];
#pragma unroll
    for (int j = 0; j < 4; j++) {
        as_lo[j] = asrc[cg * 4 + j];
        as_hi[j] = asrc[128 + cg * 4 + j];
        ad_lo[j] = adst[cg * 4 + j];
        ad_hi[j] = adst[128 + cg * 4 + j];
    }
    int hA = cg >> 4;                           // head of low half (0/1)
    int slot = (w & 3) * 4 + cx2;               // 0..15
#pragma unroll
    for (int i = 0; i < 8; i++) {
        int r = (i < 4) ? (ry2 * 4 + i) : (32 + ry2 * 4 + (i - 4));
        float pls0 = 0, pls1 = 0, pld0 = 0, pld1 = 0;
#pragma unroll
        for (int j = 0; j < 4; j++) {
            pls0 += acc[i][j] * as_lo[j];
            pls1 += acc[i][4 + j] * as_hi[j];
            pld0 += acc[i][j] * ad_lo[j];
            pld1 += acc[i][4 + j] * ad_hi[j];
        }
        redls[r][hA][slot] = pls0;
        redls[r][2 + hA][slot] = pls1;
        redld[r][hA][slot] = pld0;
        redld[r][2 + hA][slot] = pld1;
    }
    __syncthreads();
    {
        int r = tid >> 2, h = tid & 3;
        float s = 0, d = 0;
#pragma unroll
        for (int k = 0; k < 16; k++) { s += redls[r][h][k]; d += redld[r][h][k]; }
        g_ls[(rowBase + r) * 4 + h] = s;
        g_ld[(rowBase + r) * 4 + h] = d;
    }
}

// ---------------- softmax edge records, all 4 heads per graph ----------------
// grid GG; 512 threads; thread-per-node; ls/ld staged in smem.
// Writes g_ew[(g,h)][j] = (expWeight, srcBits) and g_snorm[(g,h)][n] = 1/sum.
__global__ void __launch_bounds__(512) k_weights2() {
    __shared__ float sls[HEADS][1024];
    __shared__ float sld[HEADS][1024];
    int g = blockIdx.x;
    size_t gb = (size_t)g * NN;
    int tid = threadIdx.x;
    const float* __restrict__ lsrc = g_ls + gb * HEADS;
    const float* __restrict__ ldsr = g_ld + gb * HEADS;
    for (int i = tid; i < NN * HEADS; i += 512) {
        int n = i >> 2, h = i & 3;
        sls[h][n] = lsrc[i];
        sld[h][n] = ldsr[i];
    }
    __syncthreads();

    float2* __restrict__ ew0 = g_ew + (size_t)(g * HEADS + 0) * EP;
    float2* __restrict__ ew1 = g_ew + (size_t)(g * HEADS + 1) * EP;
    float2* __restrict__ ew2 = g_ew + (size_t)(g * HEADS + 2) * EP;
    float2* __restrict__ ew3 = g_ew + (size_t)(g * HEADS + 3) * EP;

    for (int n = tid; n < NN; n += 512) {
        int s0 = g_off[n], s1 = g_off[n + 1];
        float ld0 = sld[0][n], ld1 = sld[1][n], ld2 = sld[2][n], ld3 = sld[3][n];
        float sm0 = 0.f, sm1 = 0.f, sm2 = 0.f, sm3 = 0.f;
        for (int j = s0; j < s1; j++) {
            int s = g_srcList[j];
            float sb = __int_as_float(s);
            float v0 = sls[0][s] + ld0; v0 = v0 > 0.f ? v0 : 0.2f * v0;
            float v1 = sls[1][s] + ld1; v1 = v1 > 0.f ? v1 : 0.2f * v1;
            float v2 = sls[2][s] + ld2; v2 = v2 > 0.f ? v2 : 0.2f * v2;
            float v3 = sls[3][s] + ld3; v3 = v3 > 0.f ? v3 : 0.2f * v3;
            float w0 = __expf(v0), w1 = __expf(v1), w2 = __expf(v2), w3 = __expf(v3);
            ew0[j] = make_float2(w0, sb);
            ew1[j] = make_float2(w1, sb);
            ew2[j] = make_float2(w2, sb);
            ew3[j] = make_float2(w3, sb);
            sm0 += w0; sm1 += w1; sm2 += w2; sm3 += w3;
        }
        g_snorm[(size_t)(g * HEADS + 0) * NN + n] = 1.f / (sm0 + 1e-16f);
        g_snorm[(size_t)(g * HEADS + 1) * NN + n] = 1.f / (sm1 + 1e-16f);
        g_snorm[(size_t)(g * HEADS + 2) * NN + n] = 1.f / (sm2 + 1e-16f);
        g_snorm[(size_t)(g * HEADS + 3) * NN + n] = 1.f / (sm3 + 1e-16f);
    }
}

// ---------------- GAT aggregate: slice-major, float2 edge records ------------
// grid (GG, 16): slice sl, head h = sl>>2. 512 threads; half-warp per node.
__global__ void __launch_bounds__(512) k_gat_agg4() {
    extern __shared__ float Hs[];               // [1000][16]
    int g = blockIdx.x, sl = blockIdx.y;
    int h = sl >> 2;
    int tid = threadIdx.x;
    int lane = tid & 31, w = tid >> 5;
    int half = lane >> 4, ch = lane & 15;
    size_t gb = (size_t)g * NN;
    float* __restrict__ Hsl = g_H + (size_t)sl * HSLICE + gb * 16;

    // Phase A: fully coalesced contiguous 64KB copy
    const float4* src4 = (const float4*)Hsl;
    for (int idx = tid; idx < NN * 4; idx += 512)
        ((float4*)Hs)[idx] = src4[idx];
    __syncthreads();

    const float2* __restrict__ ew = g_ew + (size_t)(g * HEADS + h) * EP;
    const float* __restrict__ nrm = g_snorm + (size_t)(g * HEADS + h) * NN;

    // Phase B: half-warp per node SpMM
    for (int n = w * 2 + half; n < NN; n += 32) {
        int s0 = g_off[n], s1 = g_off[n + 1];
        float acc = 0.f;
        int j = s0;
        for (; j + 2 <= s1; j += 2) {
            float2 e0 = ew[j], e1 = ew[j + 1];
            acc += e0.x * Hs[__float_as_int(e0.y) * 16 + ch]
                 + e1.x * Hs[__float_as_int(e1.y) * 16 + ch];
        }
        if (j < s1) {
            float2 e0 = ew[j];
            acc += e0.x * Hs[__float_as_int(e0.y) * 16 + ch];
        }
        Hsl[n * 16 + ch] = acc * nrm[n];        // in-place, coalesced
    }
}

// ---------------- head mean + bias + elu -> X ----------------
__global__ void k_finish(const float* __restrict__ bg_l, int outBuf) {
    float* __restrict__ Xout = outBuf ? g_X1 : g_X0;
    int tid = threadIdx.x;
    int r = blockIdx.x * 4 + (tid >> 6);
    int c = tid & 63;
    float v = 0.f;
#pragma unroll
    for (int h = 0; h < HEADS; h++) {
        int cc = h * 64 + c;
        v += g_H[(size_t)(cc >> 4) * HSLICE + (size_t)r * 16 + (cc & 15)];
    }
    v = 0.25f * v + bg_l[c];
    v = v > 0.f ? v : expm1f(v);
    Xout[(size_t)r * 64 + c] = v;
}

// ---------------- GI split-K GEMM (transposed smem, float4 frags) ------------
__global__ void __launch_bounds__(256) k_gi_gemm(const float* __restrict__ Wih) {
    __shared__ float As[32][68];
    __shared__ float Ws[32][68];
    int kBase = blockIdx.x * KCH;
    int gateBase = blockIdx.y * 64;
    int tid = threadIdx.x;
    int tx = tid & 15, ty = tid >> 4;
    float acc[4][4] = {};
    for (int kt = 0; kt < KCH / 32; kt++) {
        int k0 = kBase + kt * 32;
        __syncthreads();
#pragma unroll
        for (int i = 0; i < 8; i++) {
            int idx = tid + i * 256;
            int r = idx >> 5, kk = idx & 31;
            As[kk][r] = g_X1[r * NH + k0 + kk];
            Ws[kk][r] = Wih[(size_t)(gateBase + r) * NH + k0 + kk];
        }
        __syncthreads();
#pragma unroll
        for (int kk = 0; kk < 32; kk++) {
            float4 a = *(const float4*)&As[kk][ty * 4];
            float4 wv = *(const float4*)&Ws[kk][tx * 4];
            float av[4] = {a.x, a.y, a.z, a.w};
            float bw[4] = {wv.x, wv.y, wv.z, wv.w};
#pragma unroll
            for (int i = 0; i < 4; i++)
#pragma unroll
                for (int j = 0; j < 4; j++)
                    acc[i][j] += av[i] * bw[j];
        }
    }
#pragma unroll
    for (int i = 0; i < 4; i++)
#pragma unroll
        for (int j = 0; j < 4; j++)
            g_GIpart[(blockIdx.x * GG + ty * 4 + i) * GATES + gateBase + tx * 4 + j] = acc[i][j];
}

__global__ void k_gi_reduce(const float* __restrict__ b_ih) {
    int idx = blockIdx.x * blockDim.x + threadIdx.x;
    int j = idx % GATES;
    float s = b_ih[j];
    for (int kc = 0; kc < NCHUNK; kc++)
        s += g_GIpart[kc * GG * GATES + idx];
    g_GI[idx] = s;
}

// ---------------- GRU recurrence ----------------
__global__ void __launch_bounds__(256) k_gru(const float* __restrict__ Whh,
                                             const float* __restrict__ bhh) {
    __shared__ float h[BB][HID];
    __shared__ float gh[BB][GATES];
    int tid = threadIdx.x;
    h[tid >> 6][tid & 63] = 0.f;
    __syncthreads();
    for (int t = 0; t < TT; t++) {
#pragma unroll
        for (int q = 0; q < 3; q++) {
            int idx = tid + q * 256;
            int b = idx / GATES, j = idx % GATES;
            float s = bhh[j];
#pragma unroll
            for (int c = 0; c < HID; c++)
                s += h[b][c] * Whh[j * HID + c];
            gh[b][j] = s;
        }
        __syncthreads();
        int b = tid >> 6, c = tid & 63;
        int g = b * TT + t;
        float ir = g_GI[g * GATES + c]        + gh[b][c];
        float iz = g_GI[g * GATES + 64 + c]   + gh[b][64 + c];
        float in = g_GI[g * GATES + 128 + c];
        float hn = gh[b][128 + c];
        float r = 1.f / (1.f + expf(-ir));
        float z = 1.f / (1.f + expf(-iz));
        float nn = tanhf(in + r * hn);
        float hnew = (1.f - z) * nn + z * h[b][c];
        __syncthreads();
        h[b][c] = hnew;
        __syncthreads();
    }
    g_hT[tid] = h[tid >> 6][tid & 63];
}

// ---------------- final FC ----------------
__global__ void k_fc(const float* __restrict__ Wfc, const float* __restrict__ bfc,
                     float* __restrict__ out) {
    int b = blockIdx.x;
    int n = blockIdx.y * 256 + threadIdx.x;
    if (n >= NN) return;
    float s = bfc[n];
#pragma unroll
    for (int c = 0; c < HID; c++)
        s += g_hT[b * HID + c] * Wfc[c * NN + n];
    out[b * NN + n] = s;
}

// ---------------- launcher ----------------
extern "C" void kernel_launch(void* const* d_in, const int* in_sizes, int n_in,
                              void* d_out, int out_size) {
    const float* x_seq = (const float*)d_in[0];
    const int*   edge_index = (const int*)d_in[1];
    const float* W_in = (const float*)d_in[3];
    const float* b_in = (const float*)d_in[4];
    const float* Wg   = (const float*)d_in[5];
    const float* a_src= (const float*)d_in[6];
    const float* a_dst= (const float*)d_in[7];
    const float* bg   = (const float*)d_in[8];
    const float* W_ih = (const float*)d_in[9];
    const float* W_hh = (const float*)d_in[10];
    const float* b_ih = (const float*)d_in[11];
    const float* b_hh = (const float*)d_in[12];
    const float* W_fc = (const float*)d_in[13];
    const float* b_fc = (const float*)d_in[14];
    float* out = (float*)d_out;

    cudaFuncSetAttribute(k_gat_agg4,
                         cudaFuncAttributeMaxDynamicSharedMemorySize, AGG4_SMEM);

    // launch 1: fused CSR + input projection
    k_pre<<<4001, 1024>>>(edge_index, x_seq, W_in, b_in);

    // launches 2-4: gemm, weights2, agg4 (#4 = ncu slot -> agg4!)
    for (int l = 0; l < LL; l++) {
        int inBuf = l & 1;
        int outBuf = 1 - inBuf;
        k_gat_gemm<<<RR / 64, 256>>>(inBuf, Wg + (size_t)l * HID * 256,
                                     a_src + (size_t)l * HEADS * HID,
                                     a_dst + (size_t)l * HEADS * HID);
        k_weights2<<<GG, 512>>>();
        k_gat_agg4<<<dim3(GG, 16), 512, AGG4_SMEM>>>();
        k_finish<<<RR / 4, 256>>>(bg + (size_t)l * HID, outBuf);
    }
    // final features in g_X1

    k_gi_gemm<<<dim3(NCHUNK, 3), 256>>>(W_ih);
    k_gi_reduce<<<(GG * GATES) / 256, 256>>>(b_ih);
    k_gru<<<1, 256>>>(W_hh, b_hh);
    k_fc<<<dim3(BB, 4), 256>>>(W_fc, b_fc, out);
}